// round 2
// baseline (speedup 1.0000x reference)
#include <cuda_runtime.h>

typedef unsigned long long ull;

#define NB 16
#define NC 128
#define NS 16384
#define NK 64
#define XROW 132   // smem row stride (floats)

__device__ float g_cwt2[NC*2*NK];  // codewords duplicated pairs: [c][2k] = {cw,cw}
__device__ float g_cw2[NK];        // ||cw_k||^2
__device__ float g_e[NB*NK*NC];    // aggregated a^T x
__device__ float g_asum[NB*NK];    // sum_s a[b,s,k]
__device__ float g_mean[NK];
__device__ float g_rstd[NK];
__device__ float g_scale[NB*NC];

__device__ __forceinline__ void unpack2(ull v, float& lo, float& hi){
    asm("mov.b64 {%0, %1}, %2;" : "=f"(lo), "=f"(hi) : "l"(v));
}
__device__ __forceinline__ void ffma2(ull& acc, ull a, ull b){
    asm("fma.rn.f32x2 %0, %1, %2, %0;" : "+l"(acc) : "l"(a), "l"(b));
}

// ---------------------------------------------------------------- prep
__global__ void k_prep(const float* __restrict__ cw){
    int i = blockIdx.x*256 + threadIdx.x;
    if (i < NB*NK*NC) g_e[i] = 0.f;
    if (i < NB*NK)    g_asum[i] = 0.f;
    if (i < NK*NC){
        int k = i >> 7, c = i & 127;
        float v = cw[i];
        g_cwt2[c*(2*NK) + 2*k]     = v;
        g_cwt2[c*(2*NK) + 2*k + 1] = v;
    }
    if (i < NK){
        float s = 0.f;
        for (int c = 0; c < NC; c++){ float v = cw[i*NC + c]; s = fmaf(v, v, s); }
        g_cw2[i] = s;
    }
}

// ---------------------------------------------------------------- encode
// 1024 blocks (16 b x 64 tiles of 256 s), 256 threads, 2 subtiles of 128 s.
__global__ void __launch_bounds__(256,2) k_encode(const float* __restrict__ x,
                                                  const float* __restrict__ smo){
    extern __shared__ float sh[];
    float* Xs    = sh;                 // NC * XROW  (x tile, [c][s])
    float* At    = sh + NC*XROW;       // NK * XROW  (logits -> a, [k][s])
    float* x2S   = At + NK*XROW;       // 128
    float* asumS = x2S + NC;           // 64

    int tid  = threadIdx.x;
    int b    = blockIdx.x >> 6;
    int tile = blockIdx.x & 63;
    const float* xb = x + (long)b * ((long)NC * NS);

    // cross-GEMM mapping: 8 s (4 s-pairs) x 4 k per thread
    int tsg = tid & 15;     // s-chunk of 8
    int tkg = tid >> 4;     // k-chunk of 4
    // e-GEMM mapping: 4 k x 8 c per thread (s-pair accumulation)
    int kg = tid >> 4;      // k0 = 4*kg
    int cg = tid & 15;      // c = cg + 16*m

    if (tid < NK) asumS[tid] = 0.f;

    ull eacc[32];           // [4k][8c], each holds {s-even, s-odd} partial sums
    #pragma unroll
    for (int i = 0; i < 32; i++) eacc[i] = 0ULL;

    for (int sub = 0; sub < 2; sub++){
        int s0 = tile*256 + sub*128;
        __syncthreads();
        // ---- stage X tile [c][s], float4 coalesced
        for (int i = tid; i < NC*32; i += 256){
            int c = i >> 5, q = i & 31;
            float4 v = *(const float4*)(xb + (long)c*NS + s0 + 4*q);
            *(float4*)&Xs[c*XROW + 4*q] = v;
        }
        __syncthreads();
        // ---- x2 per s
        if (tid < 128){
            float s = 0.f;
            #pragma unroll 8
            for (int c = 0; c < NC; c++){ float v = Xs[c*XROW + tid]; s = fmaf(v, v, s); }
            x2S[tid] = s;
        }
        __syncthreads();
        // ---- cross GEMM -> logits (s-pair FFMA2, cw broadcast pairs, no packing)
        {
            ull cacc[16];   // [sp][kk]
            #pragma unroll
            for (int i = 0; i < 16; i++) cacc[i] = 0ULL;
            #pragma unroll 2
            for (int c = 0; c < NC; c++){
                const ulonglong2* xp = (const ulonglong2*)&Xs[c*XROW + 8*tsg];
                ulonglong2 xa = xp[0], xb2 = xp[1];          // 4 s-pairs
                const ulonglong2* wp = (const ulonglong2*)&g_cwt2[c*(2*NK) + 8*tkg];
                ulonglong2 wa = __ldg(wp), wb = __ldg(wp+1); // 4 dup k-pairs
                ffma2(cacc[0],  xa.x,  wa.x); ffma2(cacc[1],  xa.x,  wa.y); ffma2(cacc[2],  xa.x,  wb.x); ffma2(cacc[3],  xa.x,  wb.y);
                ffma2(cacc[4],  xa.y,  wa.x); ffma2(cacc[5],  xa.y,  wa.y); ffma2(cacc[6],  xa.y,  wb.x); ffma2(cacc[7],  xa.y,  wb.y);
                ffma2(cacc[8],  xb2.x, wa.x); ffma2(cacc[9],  xb2.x, wa.y); ffma2(cacc[10], xb2.x, wb.x); ffma2(cacc[11], xb2.x, wb.y);
                ffma2(cacc[12], xb2.y, wa.x); ffma2(cacc[13], xb2.y, wa.y); ffma2(cacc[14], xb2.y, wb.x); ffma2(cacc[15], xb2.y, wb.y);
            }
            // epilogue: logit = smo_k * (x2_s + cw2_k - 2*cross)
            float4 smk = *(const float4*)&smo[4*tkg];
            float4 b2k = *(const float4*)&g_cw2[4*tkg];
            float sm[4] = {smk.x, smk.y, smk.z, smk.w};
            float b2[4] = {b2k.x, b2k.y, b2k.z, b2k.w};
            #pragma unroll
            for (int sp = 0; sp < 4; sp++){
                float2 x2p = *(const float2*)&x2S[8*tsg + 2*sp];
                #pragma unroll
                for (int kk = 0; kk < 4; kk++){
                    float lo, hi; unpack2(cacc[sp*4 + kk], lo, hi);
                    float2 l;
                    l.x = sm[kk] * ((x2p.x + b2[kk]) - 2.f*lo);
                    l.y = sm[kk] * ((x2p.y + b2[kk]) - 2.f*hi);
                    *(float2*)&At[(4*tkg + kk)*XROW + 8*tsg + 2*sp] = l;
                }
            }
        }
        __syncthreads();
        // ---- softmax over k (warp per s, 2 k per lane)
        {
            int w = tid >> 5, lane = tid & 31;
            for (int s = w; s < 128; s += 8){
                float l0 = At[lane*XROW + s];
                float l1 = At[(lane+32)*XROW + s];
                float mx = fmaxf(l0, l1);
                #pragma unroll
                for (int o = 16; o > 0; o >>= 1) mx = fmaxf(mx, __shfl_xor_sync(0xffffffffu, mx, o));
                float e0 = __expf(l0 - mx), e1 = __expf(l1 - mx);
                float ss = e0 + e1;
                #pragma unroll
                for (int o = 16; o > 0; o >>= 1) ss += __shfl_xor_sync(0xffffffffu, ss, o);
                float inv = 1.f / ss;
                At[lane*XROW + s]      = e0*inv;
                At[(lane+32)*XROW + s] = e1*inv;
            }
        }
        __syncthreads();
        // ---- asum per k
        if (tid < NK){
            float s = 0.f;
            const float4* ar = (const float4*)&At[tid*XROW];
            #pragma unroll 8
            for (int q = 0; q < 32; q++){ float4 v = ar[q]; s += (v.x+v.y)+(v.z+v.w); }
            asumS[tid] += s;
        }
        // ---- e GEMM: eacc{s,s+1}[k][c] += a{s,s+1} * x{s,s+1}  (pure ulonglong2, no packs)
        {
            #pragma unroll 2
            for (int q = 0; q < 32; q++){
                ulonglong2 a0 = *(const ulonglong2*)&At[(4*kg+0)*XROW + 4*q];
                ulonglong2 a1 = *(const ulonglong2*)&At[(4*kg+1)*XROW + 4*q];
                ulonglong2 a2 = *(const ulonglong2*)&At[(4*kg+2)*XROW + 4*q];
                ulonglong2 a3 = *(const ulonglong2*)&At[(4*kg+3)*XROW + 4*q];
                #pragma unroll
                for (int m = 0; m < 8; m++){
                    ulonglong2 xv = *(const ulonglong2*)&Xs[(cg + 16*m)*XROW + 4*q];
                    ffma2(eacc[0*8+m], a0.x, xv.x); ffma2(eacc[0*8+m], a0.y, xv.y);
                    ffma2(eacc[1*8+m], a1.x, xv.x); ffma2(eacc[1*8+m], a1.y, xv.y);
                    ffma2(eacc[2*8+m], a2.x, xv.x); ffma2(eacc[2*8+m], a2.y, xv.y);
                    ffma2(eacc[3*8+m], a3.x, xv.x); ffma2(eacc[3*8+m], a3.y, xv.y);
                }
            }
        }
    }
    // ---- block partials -> global
    float* ge = g_e + b*NK*NC;
    #pragma unroll
    for (int kk = 0; kk < 4; kk++){
        int k = 4*kg + kk;
        #pragma unroll
        for (int m = 0; m < 8; m++){
            float lo, hi; unpack2(eacc[kk*8 + m], lo, hi);
            atomicAdd(&ge[k*NC + cg + 16*m], lo + hi);
        }
    }
    if (tid < NK) atomicAdd(&g_asum[b*NK + tid], asumS[tid]);
}

// ---------------------------------------------------------------- BN stats
__global__ void k_bnstats(const float* __restrict__ cw){
    int k = blockIdx.x, tid = threadIdx.x;
    float s = 0.f, s2 = 0.f;
    for (int i = tid; i < NB*NC; i += 256){
        int b = i >> 7, c = i & 127;
        float ev = g_e[b*NK*NC + k*NC + c] - g_asum[b*NK + k]*cw[k*NC + c];
        s += ev; s2 = fmaf(ev, ev, s2);
    }
    __shared__ float rs[8], rs2[8];
    #pragma unroll
    for (int o = 16; o > 0; o >>= 1){
        s  += __shfl_xor_sync(0xffffffffu, s,  o);
        s2 += __shfl_xor_sync(0xffffffffu, s2, o);
    }
    int w = tid >> 5;
    if ((tid & 31) == 0){ rs[w] = s; rs2[w] = s2; }
    __syncthreads();
    if (tid == 0){
        float S = 0.f, S2 = 0.f;
        for (int i = 0; i < 8; i++){ S += rs[i]; S2 += rs2[i]; }
        float mean = S * (1.f/2048.f);
        float var  = S2 * (1.f/2048.f) - mean*mean;
        g_mean[k] = mean;
        g_rstd[k] = rsqrtf(var + 1e-5f);
    }
}

// ---------------------------------------------------------------- BN+relu+mean+FC+sigmoid
// one block per b, 256 threads; fcw staged in padded smem (conflict/coalesce-free)
__global__ void k_scalecalc(const float* __restrict__ cw,  const float* __restrict__ bnw,
                            const float* __restrict__ bnb, const float* __restrict__ fcw,
                            const float* __restrict__ fcb){
    extern __shared__ float shs[];
    float* fcwS = shs;            // 128 * 129
    float* en   = shs + NC*129;   // 128
    int b = blockIdx.x, tid = threadIdx.x;

    for (int g = tid; g < NC*NC; g += 256){
        int c = g >> 7, j = g & 127;
        fcwS[c*129 + j] = fcw[g];
    }
    if (tid < NC){
        int c = tid;
        float acc = 0.f;
        #pragma unroll 8
        for (int k = 0; k < NK; k++){
            float ev = g_e[b*NK*NC + k*NC + c] - g_asum[b*NK + k]*cw[k*NC + c];
            float bn = (ev - g_mean[k]) * g_rstd[k] * bnw[k] + bnb[k];
            acc += fmaxf(bn, 0.f);
        }
        en[c] = acc * (1.f/64.f);
    }
    __syncthreads();
    if (tid < NC){
        int c = tid;
        float o = fcb[c];
        #pragma unroll 8
        for (int j = 0; j < NC; j++) o = fmaf(en[j], fcwS[c*129 + j], o);
        g_scale[b*NC + c] = 1.f / (1.f + expf(-o));
    }
}

// ---------------------------------------------------------------- apply scale
__global__ void k_apply(const float* __restrict__ x, float* __restrict__ out){
    long i = (long)blockIdx.x*256 + threadIdx.x;   // float4 index
    float4 v = ((const float4*)x)[i];
    float sc = g_scale[i >> 12];
    float4 o; o.x = v.x*sc; o.y = v.y*sc; o.z = v.z*sc; o.w = v.w*sc;
    ((float4*)out)[i] = o;
}

// ---------------------------------------------------------------- launch
extern "C" void kernel_launch(void* const* d_in, const int* in_sizes, int n_in,
                              void* d_out, int out_size){
    const float* x   = (const float*)d_in[0];
    const float* cw  = (const float*)d_in[1];
    const float* smo = (const float*)d_in[2];
    const float* bnw = (const float*)d_in[3];
    const float* bnb = (const float*)d_in[4];
    const float* fcw = (const float*)d_in[5];
    const float* fcb = (const float*)d_in[6];
    float* out = (float*)d_out;

    const int smem_enc = (NC*XROW + NK*XROW + NC + NK) * 4;   // 102144
    const int smem_sc  = (NC*129 + NC) * 4;                   // 66560
    cudaFuncSetAttribute(k_encode,    cudaFuncAttributeMaxDynamicSharedMemorySize, smem_enc);
    cudaFuncSetAttribute(k_scalecalc, cudaFuncAttributeMaxDynamicSharedMemorySize, smem_sc);

    k_prep<<<516, 256>>>(cw);
    k_encode<<<1024, 256, smem_enc>>>(x, smo);
    k_bnstats<<<64, 256>>>(cw);
    k_scalecalc<<<16, 256, smem_sc>>>(cw, bnw, bnb, fcw, fcb);
    k_apply<<<32768, 256>>>(x, out);
}

// round 3
// speedup vs baseline: 1.0124x; 1.0124x over previous
#include <cuda_runtime.h>

typedef unsigned long long ull;

#define NB 16
#define NC 128
#define NS 16384
#define NK 64
#define XROW 132   // smem row stride (floats)

__device__ float g_cwt2[NC*2*NK];  // codewords duplicated pairs: [c][2k] = {cw,cw}
__device__ float g_cw2[NK];        // ||cw_k||^2
__device__ float g_e[NB*NK*NC];    // aggregated a^T x
__device__ float g_asum[NB*NK];    // sum_s a[b,s,k]
__device__ float g_mean[NK];
__device__ float g_rstd[NK];
__device__ float g_scale[NB*NC];

__device__ __forceinline__ void unpack2(ull v, float& lo, float& hi){
    asm("mov.b64 {%0, %1}, %2;" : "=f"(lo), "=f"(hi) : "l"(v));
}
__device__ __forceinline__ void ffma2(ull& acc, ull a, ull b){
    asm("fma.rn.f32x2 %0, %1, %2, %0;" : "+l"(acc) : "l"(a), "l"(b));
}

// ---------------------------------------------------------------- prep
__global__ void k_prep(const float* __restrict__ cw){
    int i = blockIdx.x*256 + threadIdx.x;
    if (i < NB*NK*NC) g_e[i] = 0.f;
    if (i < NB*NK)    g_asum[i] = 0.f;
    if (i < NK*NC){
        int k = i >> 7, c = i & 127;
        float v = cw[i];
        g_cwt2[c*(2*NK) + 2*k]     = v;
        g_cwt2[c*(2*NK) + 2*k + 1] = v;
    }
    if (i < NK){
        float s = 0.f;
        for (int c = 0; c < NC; c++){ float v = cw[i*NC + c]; s = fmaf(v, v, s); }
        g_cw2[i] = s;
    }
}

// ---------------------------------------------------------------- encode
// 1024 blocks (16 b x 64 tiles of 256 s), 256 threads, 2 subtiles of 128 s.
__global__ void __launch_bounds__(256,2) k_encode(const float* __restrict__ x,
                                                  const float* __restrict__ smo){
    extern __shared__ float sh[];
    float* Xs    = sh;                 // NC * XROW  (x tile, [c][s])
    float* At    = sh + NC*XROW;       // NK * XROW  (logits -> a, [k][s])
    float* x2S   = At + NK*XROW;       // 128
    float* asumS = x2S + NC;           // 64

    int tid  = threadIdx.x;
    int b    = blockIdx.x >> 6;
    int tile = blockIdx.x & 63;
    const float* xb = x + (long)b * ((long)NC * NS);

    // cross-GEMM mapping: 8 s (4 s-pairs) x 4 k per thread
    int tsg = tid & 15;     // s-chunk of 8
    int tkg = tid >> 4;     // k-chunk of 4
    // e-GEMM mapping: 4 k x 8 c per thread (s-pair accumulation)
    int kg = tid >> 4;      // k0 = 4*kg
    int cg = tid & 15;      // c = cg + 16*m

    if (tid < NK) asumS[tid] = 0.f;

    ull eacc[32];           // [4k][8c], each holds {s-even, s-odd} partial sums
    #pragma unroll
    for (int i = 0; i < 32; i++) eacc[i] = 0ULL;

    for (int sub = 0; sub < 2; sub++){
        int s0 = tile*256 + sub*128;
        __syncthreads();
        // ---- stage X tile [c][s], float4 coalesced
        for (int i = tid; i < NC*32; i += 256){
            int c = i >> 5, q = i & 31;
            float4 v = *(const float4*)(xb + (long)c*NS + s0 + 4*q);
            *(float4*)&Xs[c*XROW + 4*q] = v;
        }
        __syncthreads();
        // ---- x2 per s
        if (tid < 128){
            float s = 0.f;
            #pragma unroll 8
            for (int c = 0; c < NC; c++){ float v = Xs[c*XROW + tid]; s = fmaf(v, v, s); }
            x2S[tid] = s;
        }
        __syncthreads();
        // ---- cross GEMM -> logits (s-pair FFMA2, cw broadcast pairs, no packing)
        {
            ull cacc[16];   // [sp][kk]
            #pragma unroll
            for (int i = 0; i < 16; i++) cacc[i] = 0ULL;
            #pragma unroll 2
            for (int c = 0; c < NC; c++){
                const ulonglong2* xp = (const ulonglong2*)&Xs[c*XROW + 8*tsg];
                ulonglong2 xa = xp[0], xb2 = xp[1];          // 4 s-pairs
                const ulonglong2* wp = (const ulonglong2*)&g_cwt2[c*(2*NK) + 8*tkg];
                ulonglong2 wa = __ldg(wp), wb = __ldg(wp+1); // 4 dup k-pairs
                ffma2(cacc[0],  xa.x,  wa.x); ffma2(cacc[1],  xa.x,  wa.y); ffma2(cacc[2],  xa.x,  wb.x); ffma2(cacc[3],  xa.x,  wb.y);
                ffma2(cacc[4],  xa.y,  wa.x); ffma2(cacc[5],  xa.y,  wa.y); ffma2(cacc[6],  xa.y,  wb.x); ffma2(cacc[7],  xa.y,  wb.y);
                ffma2(cacc[8],  xb2.x, wa.x); ffma2(cacc[9],  xb2.x, wa.y); ffma2(cacc[10], xb2.x, wb.x); ffma2(cacc[11], xb2.x, wb.y);
                ffma2(cacc[12], xb2.y, wa.x); ffma2(cacc[13], xb2.y, wa.y); ffma2(cacc[14], xb2.y, wb.x); ffma2(cacc[15], xb2.y, wb.y);
            }
            // epilogue: logit = smo_k * (x2_s + cw2_k - 2*cross)
            float4 smk = *(const float4*)&smo[4*tkg];
            float4 b2k = *(const float4*)&g_cw2[4*tkg];
            float sm[4] = {smk.x, smk.y, smk.z, smk.w};
            float b2[4] = {b2k.x, b2k.y, b2k.z, b2k.w};
            #pragma unroll
            for (int sp = 0; sp < 4; sp++){
                float2 x2p = *(const float2*)&x2S[8*tsg + 2*sp];
                #pragma unroll
                for (int kk = 0; kk < 4; kk++){
                    float lo, hi; unpack2(cacc[sp*4 + kk], lo, hi);
                    float2 l;
                    l.x = sm[kk] * ((x2p.x + b2[kk]) - 2.f*lo);
                    l.y = sm[kk] * ((x2p.y + b2[kk]) - 2.f*hi);
                    *(float2*)&At[(4*tkg + kk)*XROW + 8*tsg + 2*sp] = l;
                }
            }
        }
        __syncthreads();
        // ---- softmax over k (warp per s, 2 k per lane)
        {
            int w = tid >> 5, lane = tid & 31;
            for (int s = w; s < 128; s += 8){
                float l0 = At[lane*XROW + s];
                float l1 = At[(lane+32)*XROW + s];
                float mx = fmaxf(l0, l1);
                #pragma unroll
                for (int o = 16; o > 0; o >>= 1) mx = fmaxf(mx, __shfl_xor_sync(0xffffffffu, mx, o));
                float e0 = __expf(l0 - mx), e1 = __expf(l1 - mx);
                float ss = e0 + e1;
                #pragma unroll
                for (int o = 16; o > 0; o >>= 1) ss += __shfl_xor_sync(0xffffffffu, ss, o);
                float inv = 1.f / ss;
                At[lane*XROW + s]      = e0*inv;
                At[(lane+32)*XROW + s] = e1*inv;
            }
        }
        __syncthreads();
        // ---- asum per k
        if (tid < NK){
            float s = 0.f;
            const float4* ar = (const float4*)&At[tid*XROW];
            #pragma unroll 8
            for (int q = 0; q < 32; q++){ float4 v = ar[q]; s += (v.x+v.y)+(v.z+v.w); }
            asumS[tid] += s;
        }
        // ---- e GEMM: eacc{s,s+1}[k][c] += a{s,s+1} * x{s,s+1}  (pure ulonglong2, no packs)
        {
            #pragma unroll 2
            for (int q = 0; q < 32; q++){
                ulonglong2 a0 = *(const ulonglong2*)&At[(4*kg+0)*XROW + 4*q];
                ulonglong2 a1 = *(const ulonglong2*)&At[(4*kg+1)*XROW + 4*q];
                ulonglong2 a2 = *(const ulonglong2*)&At[(4*kg+2)*XROW + 4*q];
                ulonglong2 a3 = *(const ulonglong2*)&At[(4*kg+3)*XROW + 4*q];
                #pragma unroll
                for (int m = 0; m < 8; m++){
                    ulonglong2 xv = *(const ulonglong2*)&Xs[(cg + 16*m)*XROW + 4*q];
                    ffma2(eacc[0*8+m], a0.x, xv.x); ffma2(eacc[0*8+m], a0.y, xv.y);
                    ffma2(eacc[1*8+m], a1.x, xv.x); ffma2(eacc[1*8+m], a1.y, xv.y);
                    ffma2(eacc[2*8+m], a2.x, xv.x); ffma2(eacc[2*8+m], a2.y, xv.y);
                    ffma2(eacc[3*8+m], a3.x, xv.x); ffma2(eacc[3*8+m], a3.y, xv.y);
                }
            }
        }
    }
    // ---- block partials -> global
    float* ge = g_e + b*NK*NC;
    #pragma unroll
    for (int kk = 0; kk < 4; kk++){
        int k = 4*kg + kk;
        #pragma unroll
        for (int m = 0; m < 8; m++){
            float lo, hi; unpack2(eacc[kk*8 + m], lo, hi);
            atomicAdd(&ge[k*NC + cg + 16*m], lo + hi);
        }
    }
    if (tid < NK) atomicAdd(&g_asum[b*NK + tid], asumS[tid]);
}

// ---------------------------------------------------------------- BN stats
__global__ void k_bnstats(const float* __restrict__ cw){
    int k = blockIdx.x, tid = threadIdx.x;
    float s = 0.f, s2 = 0.f;
    for (int i = tid; i < NB*NC; i += 256){
        int b = i >> 7, c = i & 127;
        float ev = g_e[b*NK*NC + k*NC + c] - g_asum[b*NK + k]*cw[k*NC + c];
        s += ev; s2 = fmaf(ev, ev, s2);
    }
    __shared__ float rs[8], rs2[8];
    #pragma unroll
    for (int o = 16; o > 0; o >>= 1){
        s  += __shfl_xor_sync(0xffffffffu, s,  o);
        s2 += __shfl_xor_sync(0xffffffffu, s2, o);
    }
    int w = tid >> 5;
    if ((tid & 31) == 0){ rs[w] = s; rs2[w] = s2; }
    __syncthreads();
    if (tid == 0){
        float S = 0.f, S2 = 0.f;
        for (int i = 0; i < 8; i++){ S += rs[i]; S2 += rs2[i]; }
        float mean = S * (1.f/2048.f);
        float var  = S2 * (1.f/2048.f) - mean*mean;
        g_mean[k] = mean;
        g_rstd[k] = rsqrtf(var + 1e-5f);
    }
}

// ---------------------------------------------------------------- BN+relu+mean+FC+sigmoid
// one block per b, 256 threads; fcw staged in padded smem (conflict/coalesce-free)
__global__ void k_scalecalc(const float* __restrict__ cw,  const float* __restrict__ bnw,
                            const float* __restrict__ bnb, const float* __restrict__ fcw,
                            const float* __restrict__ fcb){
    extern __shared__ float shs[];
    float* fcwS = shs;            // 128 * 129
    float* en   = shs + NC*129;   // 128
    int b = blockIdx.x, tid = threadIdx.x;

    for (int g = tid; g < NC*NC; g += 256){
        int c = g >> 7, j = g & 127;
        fcwS[c*129 + j] = fcw[g];
    }
    if (tid < NC){
        int c = tid;
        float acc = 0.f;
        #pragma unroll 8
        for (int k = 0; k < NK; k++){
            float ev = g_e[b*NK*NC + k*NC + c] - g_asum[b*NK + k]*cw[k*NC + c];
            float bn = (ev - g_mean[k]) * g_rstd[k] * bnw[k] + bnb[k];
            acc += fmaxf(bn, 0.f);
        }
        en[c] = acc * (1.f/64.f);
    }
    __syncthreads();
    if (tid < NC){
        int c = tid;
        float o = fcb[c];
        #pragma unroll 8
        for (int j = 0; j < NC; j++) o = fmaf(en[j], fcwS[c*129 + j], o);
        g_scale[b*NC + c] = 1.f / (1.f + expf(-o));
    }
}

// ---------------------------------------------------------------- apply scale
__global__ void k_apply(const float* __restrict__ x, float* __restrict__ out){
    long i = (long)blockIdx.x*256 + threadIdx.x;   // float4 index
    float4 v = ((const float4*)x)[i];
    float sc = g_scale[i >> 12];
    float4 o; o.x = v.x*sc; o.y = v.y*sc; o.z = v.z*sc; o.w = v.w*sc;
    ((float4*)out)[i] = o;
}

// ---------------------------------------------------------------- launch
extern "C" void kernel_launch(void* const* d_in, const int* in_sizes, int n_in,
                              void* d_out, int out_size){
    const float* x   = (const float*)d_in[0];
    const float* cw  = (const float*)d_in[1];
    const float* smo = (const float*)d_in[2];
    const float* bnw = (const float*)d_in[3];
    const float* bnb = (const float*)d_in[4];
    const float* fcw = (const float*)d_in[5];
    const float* fcb = (const float*)d_in[6];
    float* out = (float*)d_out;

    const int smem_enc = (NC*XROW + NK*XROW + NC + NK) * 4;   // 102144
    const int smem_sc  = (NC*129 + NC) * 4;                   // 66560
    cudaFuncSetAttribute(k_encode,    cudaFuncAttributeMaxDynamicSharedMemorySize, smem_enc);
    cudaFuncSetAttribute(k_scalecalc, cudaFuncAttributeMaxDynamicSharedMemorySize, smem_sc);

    k_prep<<<516, 256>>>(cw);
    k_encode<<<1024, 256, smem_enc>>>(x, smo);
    k_bnstats<<<64, 256>>>(cw);
    k_scalecalc<<<16, 256, smem_sc>>>(cw, bnw, bnb, fcw, fcb);
    k_apply<<<32768, 256>>>(x, out);
}

// round 10
// speedup vs baseline: 1.7262x; 1.7050x over previous
#include <cuda_runtime.h>
#include <cstdint>

typedef unsigned int u32;

#define NB 16
#define NC 128
#define NS 16384
#define NK 64
#define STILE 128
#define TPC 4
#define GRPS ((NS/STILE)/TPC)      // 32
#define NCTA (NB*GRPS)             // 512

#define XSTR 136                   // word stride, mod 32 = 8
#define CWSTR 132                  // word stride, mod 32 = 4

// smem word offsets
#define W_CW    0                          // 64*132   = 8448
#define W_XS    (W_CW + NK*CWSTR)          // 128*136  = 17408
#define W_AT    (W_XS + NC*XSTR)           // 64*136   = 8704
#define W_X2    (W_AT + NK*XSTR)           // 128
#define W_X2P   (W_X2 + 128)               // 8*32*4 = 1024
#define W_SM2   (W_X2P + 1024)             // 64*2 = 128
#define SMEM_WORDS (W_SM2 + 128)
#define SMEM_BYTES (SMEM_WORDS*4)          // ~144 KB

__device__ float g_cw2[NK];
__device__ float g_e[NB*NK*NC];
__device__ float g_asum[NB*NK];
__device__ float g_mean[NK];
__device__ float g_rstd[NK];
__device__ float g_en[NB*NC];
__device__ float g_scale[NB*NC];

__device__ __forceinline__ u32 f2u(float v){ return __float_as_uint(v); }

// row-swizzled word offset (same form for Xs and At; stride 136)
__device__ __forceinline__ int sw_off(int row, int col){
    return row*XSTR + (col ^ (((row>>2)&7)<<2));
}

__device__ __forceinline__ void mma_tf32(float* d, const u32* a, const u32* b){
    asm volatile("mma.sync.aligned.m16n8k8.row.col.f32.tf32.tf32.f32 "
        "{%0,%1,%2,%3}, {%4,%5,%6,%7}, {%8,%9}, {%0,%1,%2,%3};"
        : "+f"(d[0]), "+f"(d[1]), "+f"(d[2]), "+f"(d[3])
        : "r"(a[0]), "r"(a[1]), "r"(a[2]), "r"(a[3]), "r"(b[0]), "r"(b[1]));
}

// ---------------------------------------------------------------- tiny kernels
__global__ void k_zero1(){
    int i = blockIdx.x*256 + threadIdx.x;
    g_e[i] = 0.f;
    if (i < NB*NK) g_asum[i] = 0.f;
}
__global__ void k_zero2(){
    int i = blockIdx.x*256 + threadIdx.x;
    g_e[65536 + i] = 0.f;
}
__global__ void k_prep_cw2(const float* __restrict__ cw){
    int k = threadIdx.x;
    if (k < NK){
        float s = 0.f;
        for (int c = 0; c < NC; c++){ float v = cw[k*NC + c]; s = fmaf(v, v, s); }
        g_cw2[k] = s;
    }
}

// ---------------------------------------------------------------- encode (mma.sync tf32)
__global__ void __launch_bounds__(256) k_encode(const float* __restrict__ x,
                                                const float* __restrict__ cw,
                                                const float* __restrict__ smo){
    extern __shared__ float sh[];
    float* cwS  = sh + W_CW;
    float* Xs   = sh + W_XS;
    float* At   = sh + W_AT;
    float* x2S  = sh + W_X2;
    float* x2P  = sh + W_X2P;
    float2* sm2 = (float2*)(sh + W_SM2);

    int tid = threadIdx.x, w = tid >> 5, lane = tid & 31;
    int g = lane >> 2, t = lane & 3;
    int b   = blockIdx.x >> 5;
    int grp = blockIdx.x & 31;
    const float* xb = x + (size_t)b * NC * NS;

    // stage codewords [k][c] (stride 132) + sm2 pairs
    for (int j = 0; j < 8; j++){
        int i = tid + 256*j;               // 2048 float4
        int k = i >> 5, q = i & 31;
        float4 v = *(const float4*)(cw + k*NC + 4*q);
        *(float4*)&cwS[k*CWSTR + 4*q] = v;
    }
    if (tid < NK){
        float s = smo[tid];
        sm2[tid] = make_float2(s, s * g_cw2[tid]);
    }

    // GEMM1 warp layout: 2(k) x 4(s); GEMM2: 4(c) x 2(k)
    int m0k = (w & 1)*32, s0w = (w >> 1)*32;
    int c0w = (w & 3)*32, k0  = (w >> 2)*32;

    float eacc[2][4][4];
    #pragma unroll
    for (int i = 0; i < 2; i++)
        #pragma unroll
        for (int j = 0; j < 4; j++)
            #pragma unroll
            for (int r = 0; r < 4; r++) eacc[i][j][r] = 0.f;
    float p0 = 0.f, p1 = 0.f;              // asum partials (k=lane, lane+32)

    __syncthreads();

    for (int tt = 0; tt < TPC; tt++){
        int s0 = (grp*TPC + tt)*STILE;
        // ---- stage X [c][s] swizzled + x2 partials (thread: fixed s-quad)
        {
            int q = tid & 31, m = tid >> 5;
            float4 xp = make_float4(0.f,0.f,0.f,0.f);
            #pragma unroll 4
            for (int j = 0; j < 16; j++){
                int c = m + 8*j;
                float4 v = *(const float4*)(xb + (size_t)c*NS + s0 + 4*q);
                *(float4*)&Xs[c*XSTR + ((4*q) ^ (((c>>2)&7)<<2))] = v;
                xp.x = fmaf(v.x,v.x,xp.x); xp.y = fmaf(v.y,v.y,xp.y);
                xp.z = fmaf(v.z,v.z,xp.z); xp.w = fmaf(v.w,v.w,xp.w);
            }
            *(float4*)&x2P[(m*32 + q)*4] = xp;
        }
        __syncthreads();
        if (tid < 128){
            float s2 = 0.f;
            #pragma unroll
            for (int m = 0; m < 8; m++) s2 += x2P[m*128 + tid];
            x2S[tid] = s2;
        }
        __syncthreads();
        // ---- GEMM1: D1[k][s] = cw . X   (K = c, 16 chunks)
        {
            float acc[2][4][4];
            #pragma unroll
            for (int i = 0; i < 2; i++)
                #pragma unroll
                for (int j = 0; j < 4; j++)
                    #pragma unroll
                    for (int r = 0; r < 4; r++) acc[i][j][r] = 0.f;
            #pragma unroll 4
            for (int kk = 0; kk < NC; kk += 8){
                u32 A[2][4], B[4][2];
                #pragma unroll
                for (int mi = 0; mi < 2; mi++){
                    int kr = m0k + 16*mi + g;
                    A[mi][0] = f2u(cwS[kr*CWSTR + kk + t]);
                    A[mi][1] = f2u(cwS[(kr+8)*CWSTR + kk + t]);
                    A[mi][2] = f2u(cwS[kr*CWSTR + kk + t + 4]);
                    A[mi][3] = f2u(cwS[(kr+8)*CWSTR + kk + t + 4]);
                }
                #pragma unroll
                for (int nj = 0; nj < 4; nj++){
                    int sc = s0w + 8*nj + g;
                    B[nj][0] = f2u(Xs[sw_off(kk + t,     sc)]);
                    B[nj][1] = f2u(Xs[sw_off(kk + t + 4, sc)]);
                }
                #pragma unroll
                for (int mi = 0; mi < 2; mi++)
                    #pragma unroll
                    for (int nj = 0; nj < 4; nj++)
                        mma_tf32(acc[mi][nj], A[mi], B[nj]);
            }
            // epilogue: logits into At (swizzled)
            #pragma unroll
            for (int mi = 0; mi < 2; mi++){
                int kr = m0k + 16*mi + g;
                float2 sma = sm2[kr], smb = sm2[kr+8];
                #pragma unroll
                for (int nj = 0; nj < 4; nj++){
                    int sc = s0w + 8*nj + 2*t;
                    float xa = x2S[sc], xbv = x2S[sc+1];
                    float* a4 = acc[mi][nj];
                    float2 l0, l1;
                    l0.x = fmaf(sma.x, fmaf(-2.f, a4[0], xa),  sma.y);
                    l0.y = fmaf(sma.x, fmaf(-2.f, a4[1], xbv), sma.y);
                    l1.x = fmaf(smb.x, fmaf(-2.f, a4[2], xa),  smb.y);
                    l1.y = fmaf(smb.x, fmaf(-2.f, a4[3], xbv), smb.y);
                    *(float2*)&At[sw_off(kr,   sc)] = l0;
                    *(float2*)&At[sw_off(kr+8, sc)] = l1;
                }
            }
        }
        __syncthreads();
        // ---- softmax over k (warp per s-column; lane = k, k+32)
        #pragma unroll 2
        for (int j = 0; j < 16; j++){
            int s = w*16 + j;
            float l0 = At[sw_off(lane,      s)];
            float l1 = At[sw_off(lane + 32, s)];
            float mx = fmaxf(l0, l1);
            #pragma unroll
            for (int o = 16; o > 0; o >>= 1) mx = fmaxf(mx, __shfl_xor_sync(0xffffffffu, mx, o));
            float e0 = __expf(l0 - mx), e1 = __expf(l1 - mx);
            float ss = e0 + e1;
            #pragma unroll
            for (int o = 16; o > 0; o >>= 1) ss += __shfl_xor_sync(0xffffffffu, ss, o);
            float inv = 1.f / ss;
            e0 *= inv; e1 *= inv;
            At[sw_off(lane,      s)] = e0;
            At[sw_off(lane + 32, s)] = e1;
            p0 += e0; p1 += e1;
        }
        __syncthreads();
        // ---- GEMM2: D2[c][k] += X . a^T   (K = s, 16 chunks), persistent accum
        #pragma unroll 4
        for (int ss = 0; ss < STILE; ss += 8){
            u32 A[2][4], B[4][2];
            #pragma unroll
            for (int mi = 0; mi < 2; mi++){
                int cr = c0w + 16*mi + g;
                A[mi][0] = f2u(Xs[sw_off(cr,     ss + t)]);
                A[mi][1] = f2u(Xs[sw_off(cr + 8, ss + t)]);
                A[mi][2] = f2u(Xs[sw_off(cr,     ss + t + 4)]);
                A[mi][3] = f2u(Xs[sw_off(cr + 8, ss + t + 4)]);
            }
            #pragma unroll
            for (int nj = 0; nj < 4; nj++){
                int kc = k0 + 8*nj + g;
                B[nj][0] = f2u(At[sw_off(kc, ss + t)]);
                B[nj][1] = f2u(At[sw_off(kc, ss + t + 4)]);
            }
            #pragma unroll
            for (int mi = 0; mi < 2; mi++)
                #pragma unroll
                for (int nj = 0; nj < 4; nj++)
                    mma_tf32(eacc[mi][nj], A[mi], B[nj]);
        }
        __syncthreads();
    }
    // ---- flush
    float* ge = g_e + (size_t)b * NK * NC;
    #pragma unroll
    for (int mi = 0; mi < 2; mi++){
        int cr = c0w + 16*mi + g;
        #pragma unroll
        for (int nj = 0; nj < 4; nj++){
            int kc = k0 + 8*nj + 2*t;
            atomicAdd(&ge[kc*NC + cr],         eacc[mi][nj][0]);
            atomicAdd(&ge[(kc+1)*NC + cr],     eacc[mi][nj][1]);
            atomicAdd(&ge[kc*NC + cr + 8],     eacc[mi][nj][2]);
            atomicAdd(&ge[(kc+1)*NC + cr + 8], eacc[mi][nj][3]);
        }
    }
    atomicAdd(&g_asum[b*NK + lane],      p0);
    atomicAdd(&g_asum[b*NK + lane + 32], p1);
}

// ---------------------------------------------------------------- BN stats
__global__ void k_bnstats(const float* __restrict__ cw){
    int k = blockIdx.x, tid = threadIdx.x;
    float s = 0.f, s2 = 0.f;
    for (int i = tid; i < NB*NC; i += 256){
        int b = i >> 7, c = i & 127;
        float ev = g_e[b*NK*NC + k*NC + c] - g_asum[b*NK + k]*cw[k*NC + c];
        s += ev; s2 = fmaf(ev, ev, s2);
    }
    __shared__ float rs[8], rs2[8];
    #pragma unroll
    for (int o = 16; o > 0; o >>= 1){
        s  += __shfl_xor_sync(0xffffffffu, s,  o);
        s2 += __shfl_xor_sync(0xffffffffu, s2, o);
    }
    int w = tid >> 5;
    if ((tid & 31) == 0){ rs[w] = s; rs2[w] = s2; }
    __syncthreads();
    if (tid == 0){
        float S = 0.f, S2 = 0.f;
        for (int i = 0; i < 8; i++){ S += rs[i]; S2 += rs2[i]; }
        float mean = S * (1.f/2048.f);
        float var  = S2 * (1.f/2048.f) - mean*mean;
        g_mean[k] = mean;
        g_rstd[k] = rsqrtf(var + 1e-5f);
    }
}

// ---------------------------------------------------------------- en[b][c]
__global__ void k_en(const float* __restrict__ cw, const float* __restrict__ bnw,
                     const float* __restrict__ bnb){
    int b = blockIdx.x, c = threadIdx.x;
    float acc = 0.f;
    #pragma unroll 8
    for (int k = 0; k < NK; k++){
        float ev = g_e[b*NK*NC + k*NC + c] - g_asum[b*NK + k]*cw[k*NC + c];
        float bn = (ev - g_mean[k]) * g_rstd[k] * bnw[k] + bnb[k];
        acc += fmaxf(bn, 0.f);
    }
    g_en[b*NC + c] = acc * (1.f/64.f);
}

// ---------------------------------------------------------------- FC + sigmoid
__global__ void k_fc(const float* __restrict__ fcw, const float* __restrict__ fcb){
    int idx  = blockIdx.x*8 + (threadIdx.x >> 5);
    int lane = threadIdx.x & 31;
    int b = idx >> 7, c = idx & 127;
    float4 ea = *(const float4*)(g_en + b*NC + 4*lane);
    float4 wa = *(const float4*)(fcw  + c*NC + 4*lane);
    float d = ea.x*wa.x + ea.y*wa.y + ea.z*wa.z + ea.w*wa.w;
    #pragma unroll
    for (int o = 16; o > 0; o >>= 1) d += __shfl_xor_sync(0xffffffffu, d, o);
    if (lane == 0)
        g_scale[idx] = 1.f / (1.f + expf(-(d + fcb[c])));
}

// ---------------------------------------------------------------- apply
__global__ void k_apply(const float* __restrict__ x, float* __restrict__ out){
    long i = (long)blockIdx.x*256 + threadIdx.x;
    float4 v = ((const float4*)x)[i];
    float sc = g_scale[i >> 12];
    float4 o; o.x = v.x*sc; o.y = v.y*sc; o.z = v.z*sc; o.w = v.w*sc;
    ((float4*)out)[i] = o;
}

// ---------------------------------------------------------------- launch
extern "C" void kernel_launch(void* const* d_in, const int* in_sizes, int n_in,
                              void* d_out, int out_size){
    const float* x   = (const float*)d_in[0];
    const float* cw  = (const float*)d_in[1];
    const float* smo = (const float*)d_in[2];
    const float* bnw = (const float*)d_in[3];
    const float* bnb = (const float*)d_in[4];
    const float* fcw = (const float*)d_in[5];
    const float* fcb = (const float*)d_in[6];
    float* out = (float*)d_out;

    cudaFuncSetAttribute(k_encode, cudaFuncAttributeMaxDynamicSharedMemorySize, SMEM_BYTES);

    k_zero1<<<256, 256>>>();
    k_zero2<<<256, 256>>>();
    k_prep_cw2<<<1, 64>>>(cw);
    k_encode<<<NCTA, 256, SMEM_BYTES>>>(x, cw, smo);   // ncu capture slot (s=5)
    k_bnstats<<<64, 256>>>(cw);
    k_en<<<NB, 128>>>(cw, bnw, bnb);
    k_fc<<<256, 256>>>(fcw, fcb);
    k_apply<<<32768, 256>>>(x, out);
}